// round 10
// baseline (speedup 1.0000x reference)
#include <cuda_runtime.h>
#include <math.h>
#include <stdint.h>

// ResidualVQ on B200 (sm_100 base target) — legacy tensor-core tf32
// mma.sync distance GEMM + exact reference-replica argmin rescue.
// R9: 512 threads / 16 warps per CTA (was 256/8) to fix latency binding.
//
// x: (32, 512, 1024) fp32, codebooks: (6, 1024, 512) fp32.
// out = x - residual_final, + loss & perplexity scalars appended.

#define QL      6
#define KCODES  1024
#define CD      512
#define TT      1024
#define NBATCH  32
#define NTOK    (NBATCH * TT)        // 32768
#define TILE_T  64
#define NBLK    (NTOK / TILE_T)      // 512
#define NTHR    512
#define NWARP   16
#define NPASS   2                    // code passes per layer (512 codes each)
#define PCODES  512
#define KP      8                    // c per phase (one mma k-tile)
#define NPH     (CD / KP)            // 64 phases per pass
#define BST     12                   // staged-B words per code (8 + pad)
#define RST     516                  // Rs words per token (512 + pad)
#define OUT_ELEMS (NBATCH * CD * TT)
#define MARGIN  0.25f
#define NSLOT   32                   // 2 passes x 16 warps
#define FINF    3.4e38f

// ---- smem word offsets ----
#define W_RS    0
#define W_B     (TILE_T * RST)                  // 33024
#define W_CN    (W_B + 2 * PCODES * BST)        // 45312
#define W_CV    (W_CN + KCODES)                 // 46336
#define W_CI    (W_CV + TILE_T * NSLOT * 2)     // 50432
#define W_RN    (W_CI + TILE_T * NSLOT * 2)     // 54528
#define W_IDX   (W_RN + TILE_T)
#define W_RED   (W_IDX + TILE_T)
#define W_FLAG  (W_RED + 16)
#define SMEM_WORDS (W_FLAG + 2)
#define SMEM_BYTES (SMEM_WORDS * 4)             // ~213.6 KB

__device__ float g_cbnorm[QL * KCODES];
__device__ int   g_hist[QL * KCODES];
__device__ float g_losspart[QL * NBLK];
__device__ int   g_done;

// ---------------- tensor-core helpers (sm_80+ base ISA) ----------------
__device__ __forceinline__ uint32_t f2tf(float f) {
    uint32_t r; asm("cvt.rna.tf32.f32 %0, %1;" : "=r"(r) : "f"(f)); return r;
}
__device__ __forceinline__ void mma8(float* d, uint32_t a0, uint32_t a1,
                                     uint32_t a2, uint32_t a3,
                                     uint32_t b0, uint32_t b1) {
    asm volatile(
        "mma.sync.aligned.m16n8k8.row.col.f32.tf32.tf32.f32 "
        "{%0,%1,%2,%3}, {%4,%5,%6,%7}, {%8,%9}, {%0,%1,%2,%3};"
        : "+f"(d[0]), "+f"(d[1]), "+f"(d[2]), "+f"(d[3])
        : "r"(a0), "r"(a1), "r"(a2), "r"(a3), "r"(b0), "r"(b1));
}

// ---------------- replica arithmetic (bit-matches reference) ----------------
__global__ void cbnorm_kernel(const float* __restrict__ cb) {
    int w    = (blockIdx.x * blockDim.x + threadIdx.x) >> 5;
    int lane = threadIdx.x & 31;
    if (w >= QL * KCODES) return;
    const float* row = cb + (size_t)w * CD;
    float a = 0.f;
    #pragma unroll
    for (int i = 0; i < CD / 32; i++) {
        float v = row[lane + 32 * i];
        a = __fadd_rn(a, __fmul_rn(v, v));
    }
    #pragma unroll
    for (int o = 16; o; o >>= 1)
        a = __fadd_rn(a, __shfl_down_sync(0xffffffffu, a, o));
    if (lane == 0) g_cbnorm[w] = a;
}

// Exact replica distance: serial ascending-k FFMA dot + fp32 rounding grid.
__device__ float replica_dist(const float* __restrict__ rtok,
                              const float* __restrict__ crow,
                              float Rn, float cn) {
    float m = 0.f;
    for (int c = 0; c < CD; c += 4) {
        float4 b = *(const float4*)&crow[c];
        m = __fmaf_rn(rtok[c + 0], b.x, m);
        m = __fmaf_rn(rtok[c + 1], b.y, m);
        m = __fmaf_rn(rtok[c + 2], b.z, m);
        m = __fmaf_rn(rtok[c + 3], b.w, m);
    }
    return __fadd_rn(__fsub_rn(Rn, __fmul_rn(2.f, m)), cn);
}

__device__ float block_reduce_512(float v, float* sh) {
    int t = threadIdx.x;
    #pragma unroll
    for (int o = 16; o; o >>= 1) v += __shfl_down_sync(0xffffffffu, v, o);
    if ((t & 31) == 0) sh[t >> 5] = v;
    __syncthreads();
    float r = 0.f;
    if (t < 16) {
        r = sh[t];
        #pragma unroll
        for (int o = 8; o; o >>= 1) r += __shfl_down_sync(0x0000ffffu, r, o, 16);
    }
    __syncthreads();
    return r;
}

// Merge this lane's sorted lex pair with lane^off's pair.
__device__ __forceinline__ void lexmerge2(float* v, int* idx, int off) {
    float wv0 = __shfl_xor_sync(0xffffffffu, v[0], off);
    float wv1 = __shfl_xor_sync(0xffffffffu, v[1], off);
    int   wi0 = __shfl_xor_sync(0xffffffffu, idx[0], off);
    int   wi1 = __shfl_xor_sync(0xffffffffu, idx[1], off);
    float av0 = v[0], av1 = v[1];
    int   ai0 = idx[0], ai1 = idx[1];
    // first = min of heads
    if (wv0 < av0 || (wv0 == av0 && wi0 < ai0)) {
        v[0] = wv0; idx[0] = wi0;
        // second = min(av0, wv1)
        if (av0 < wv1 || (av0 == wv1 && ai0 <= wi1)) { v[1] = av0; idx[1] = ai0; }
        else                                          { v[1] = wv1; idx[1] = wi1; }
    } else {
        // second = min(wv0, av1)
        if (wv0 < av1 || (wv0 == av1 && wi0 <= ai1)) { v[1] = wv0; idx[1] = wi0; }
        else                                          { v[1] = av1; idx[1] = ai1; }
    }
}

__device__ __forceinline__ void top2_ins(float nv, int nc, float* v, int* idx) {
    if (nv < v[0] || (nv == v[0] && nc < idx[0])) {
        v[1] = v[0]; idx[1] = idx[0]; v[0] = nv; idx[0] = nc;
    } else if (nv < v[1] || (nv == v[1] && nc < idx[1])) {
        v[1] = nv; idx[1] = nc;
    }
}

// ---------------- main kernel ----------------
__global__ __launch_bounds__(NTHR, 1)
void vq_main_kernel(const float* __restrict__ x, const float* __restrict__ cb,
                    float* __restrict__ out, int out_size) {
    extern __shared__ float smem[];
    float*    Rs   = smem + W_RS;                 // [64][516] residual
    uint32_t* Bst  = (uint32_t*)(smem + W_B);     // 2 x [512][12] tf32 bits
    float*    cn_s = smem + W_CN;                 // [1024] replica code norms
    float*    cd_v = smem + W_CV;                 // [64][32][2] cand values
    int*      cd_i = (int*)(smem + W_CI);
    float*    Rn_s = smem + W_RN;                 // [64] replica ||r||^2
    int*      idxs = (int*)(smem + W_IDX);
    float*    red  = smem + W_RED;
    int*      flag = (int*)(smem + W_FLAG);

    const int tx   = threadIdx.x;
    const int wid  = tx >> 5;
    const int lane = tx & 31;
    const int lg   = lane >> 2;    // 0..7
    const int la   = lane & 3;     // 0..3
    const int blk  = blockIdx.x;
    const int n    = blk >> 4;
    const int t0   = (blk & 15) << 6;
    const float* xblk = x + (size_t)n * CD * TT + t0;

    // ---- transpose x into Rs[tok][c] ----
    for (int it = 0; it < 16; it++) {
        int c = (tx >> 4) + 32 * it;
        int t4 = (tx & 15) * 4;
        float4 v = *(const float4*)&xblk[(size_t)c * TT + t4];
        Rs[(t4 + 0) * RST + c] = v.x;
        Rs[(t4 + 1) * RST + c] = v.y;
        Rs[(t4 + 2) * RST + c] = v.z;
        Rs[(t4 + 3) * RST + c] = v.w;
    }
    __syncthreads();

    // ---- initial replica Rn (XLA warp-reduce pattern); warp -> 4 tokens ----
    for (int t = 0; t < 4; t++) {
        int tok = wid * 4 + t;
        const float* rr = Rs + tok * RST;
        float a = 0.f;
        #pragma unroll
        for (int i = 0; i < 16; i++) {
            float r = rr[lane + 32 * i];
            a = __fadd_rn(a, __fmul_rn(r, r));
        }
        #pragma unroll
        for (int o = 16; o; o >>= 1)
            a = __fadd_rn(a, __shfl_down_sync(0xffffffffu, a, o));
        if (lane == 0) Rn_s[tok] = a;
    }
    __syncthreads();

    for (int q = 0; q < QL; q++) {
        const float* cbq = cb + (size_t)q * KCODES * CD;
        for (int i = tx; i < KCODES; i += NTHR) cn_s[i] = g_cbnorm[q * KCODES + i];
        __syncthreads();

        for (int pass = 0; pass < NPASS; pass++) {
            // warp covers codes pass*512 + wid*32 + nt*8 + lg  (nt = 0..3)
            float ac[4][4][4];
            #pragma unroll
            for (int mt = 0; mt < 4; mt++)
                #pragma unroll
                for (int nt = 0; nt < 4; nt++)
                    #pragma unroll
                    for (int e = 0; e < 4; e++) ac[mt][nt][e] = 0.f;

            // stage phase 0 directly: thread tx <-> code tx
            {
                const float* s = cbq + (size_t)(pass * PCODES + tx) * CD;
                float4 v0 = *(const float4*)s;
                float4 v1 = *(const float4*)(s + 4);
                uint4 u0 = make_uint4(f2tf(v0.x), f2tf(v0.y), f2tf(v0.z), f2tf(v0.w));
                uint4 u1 = make_uint4(f2tf(v1.x), f2tf(v1.y), f2tf(v1.z), f2tf(v1.w));
                *(uint4*)&Bst[tx * BST] = u0;
                *(uint4*)&Bst[tx * BST + 4] = u1;
            }
            __syncthreads();

            for (int p = 0; p < NPH; p++) {
                float4 pre0, pre1;
                if (p + 1 < NPH) {
                    const float* s0 = cbq + (size_t)(pass * PCODES + tx) * CD + (p + 1) * KP;
                    pre0 = *(const float4*)s0; pre1 = *(const float4*)(s0 + 4);
                }
                const uint32_t* Bb = Bst + (p & 1) * PCODES * BST;
                uint32_t b0[4], b1[4];
                #pragma unroll
                for (int nt = 0; nt < 4; nt++) {
                    uint2 bb = *(const uint2*)&Bb[(wid * 32 + nt * 8 + lg) * BST + 2 * la];
                    b0[nt] = bb.x; b1[nt] = bb.y;
                }
                const int cb0 = p * KP + 2 * la;
                #pragma unroll
                for (int mt = 0; mt < 4; mt++) {
                    int ta = 16 * mt + lg;
                    float2 lo = *(const float2*)&Rs[ta * RST + cb0];
                    float2 hi = *(const float2*)&Rs[(ta + 8) * RST + cb0];
                    uint32_t a0 = f2tf(lo.x), a2 = f2tf(lo.y);
                    uint32_t a1 = f2tf(hi.x), a3 = f2tf(hi.y);
                    #pragma unroll
                    for (int nt = 0; nt < 4; nt++)
                        mma8(ac[mt][nt], a0, a1, a2, a3, b0[nt], b1[nt]);
                }
                if (p + 1 < NPH) {
                    uint32_t* dst = Bst + ((p + 1) & 1) * PCODES * BST;
                    uint4 u0 = make_uint4(f2tf(pre0.x), f2tf(pre0.y), f2tf(pre0.z), f2tf(pre0.w));
                    uint4 u1 = make_uint4(f2tf(pre1.x), f2tf(pre1.y), f2tf(pre1.z), f2tf(pre1.w));
                    *(uint4*)&dst[tx * BST] = u0;
                    *(uint4*)&dst[tx * BST + 4] = u1;
                }
                __syncthreads();
            }

            // ---- epilogue: dist = (Rn - 2*dot) + cn ; per-warp top-2 ----
            const int slot = pass * NWARP + wid;
            #pragma unroll
            for (int mt = 0; mt < 4; mt++) {
                int tA = 16 * mt + lg, tB = tA + 8;
                float RnA = Rn_s[tA], RnB = Rn_s[tB];
                float vA[2] = {FINF, FINF}; int iA[2] = {0, 1};
                float vB[2] = {FINF, FINF}; int iB[2] = {0, 1};
                #pragma unroll
                for (int nt = 0; nt < 4; nt++) {
                    int c0 = pass * PCODES + wid * 32 + nt * 8 + 2 * la;
                    float cn0 = cn_s[c0], cn1 = cn_s[c0 + 1];
                    top2_ins((RnA - 2.f * ac[mt][nt][0]) + cn0, c0,     vA, iA);
                    top2_ins((RnA - 2.f * ac[mt][nt][1]) + cn1, c0 + 1, vA, iA);
                    top2_ins((RnB - 2.f * ac[mt][nt][2]) + cn0, c0,     vB, iB);
                    top2_ins((RnB - 2.f * ac[mt][nt][3]) + cn1, c0 + 1, vB, iB);
                }
                lexmerge2(vA, iA, 1); lexmerge2(vA, iA, 2);
                lexmerge2(vB, iB, 1); lexmerge2(vB, iB, 2);
                if (la == 0) {
                    cd_v[(tA * NSLOT + slot) * 2 + 0] = vA[0];
                    cd_v[(tA * NSLOT + slot) * 2 + 1] = vA[1];
                    cd_i[(tA * NSLOT + slot) * 2 + 0] = iA[0];
                    cd_i[(tA * NSLOT + slot) * 2 + 1] = iA[1];
                    cd_v[(tB * NSLOT + slot) * 2 + 0] = vB[0];
                    cd_v[(tB * NSLOT + slot) * 2 + 1] = vB[1];
                    cd_i[(tB * NSLOT + slot) * 2 + 0] = iB[0];
                    cd_i[(tB * NSLOT + slot) * 2 + 1] = iB[1];
                }
            }
            __syncthreads();
        }

        // ---- decision: global lex-min; margin -> exact replica rescore ----
        if (tx < TILE_T) {
            const int tok = tx;
            const float* cvp = cd_v + tok * NSLOT * 2;
            const int*   cip = cd_i + tok * NSLOT * 2;
            float v1 = FINF, v2 = FINF; int i1 = 0x7fffffff;
            for (int j = 0; j < NSLOT * 2; j++) {
                float v = cvp[j]; int c = cip[j];
                if (v < v1 || (v == v1 && c < i1)) { v2 = v1; v1 = v; i1 = c; }
                else if (v < v2) { v2 = v; }
            }
            int id = i1;
            if (v2 - v1 < MARGIN) {
                const float Rn = Rn_s[tok];
                const float* rtok = Rs + tok * RST;
                float bv = FINF; int bi = 0x7fffffff;
                float lim = v1 + MARGIN;
                for (int j = 0; j < NSLOT * 2; j++) {
                    if (cvp[j] <= lim) {
                        int c = cip[j];
                        float d = replica_dist(rtok, cbq + (size_t)c * CD, Rn, cn_s[c]);
                        if (d < bv || (d == bv && c < bi)) { bv = d; bi = c; }
                    }
                }
                id = bi;
            }
            idxs[tok] = id;
            atomicAdd(&g_hist[q * KCODES + id], 1);
        }
        __syncthreads();

        // ---- STE-replica residual update + new replica Rn ----
        for (int t = 0; t < 4; t++) {
            int tok = wid * 4 + t;
            const float* row = cbq + (size_t)idxs[tok] * CD;
            float* rr = Rs + tok * RST;
            float a = 0.f;
            #pragma unroll
            for (int i = 0; i < 16; i++) {
                int c = lane + 32 * i;
                float r  = rr[c];
                float xd = row[c];
                float tt = __fsub_rn(xd, r);
                float qv = __fadd_rn(r, tt);
                float rn = __fsub_rn(r, qv);
                rr[c] = rn;
                a = __fadd_rn(a, __fmul_rn(rn, rn));
            }
            #pragma unroll
            for (int o = 16; o; o >>= 1)
                a = __fadd_rn(a, __shfl_down_sync(0xffffffffu, a, o));
            if (lane == 0) Rn_s[tok] = a;
        }
        __syncthreads();
        if (tx < 32) {
            float s = Rn_s[tx] + Rn_s[tx + 32];
            #pragma unroll
            for (int o = 16; o; o >>= 1) s += __shfl_down_sync(0xffffffffu, s, o);
            if (tx == 0) g_losspart[q * NBLK + blk] = s;
        }
        __syncthreads();
    }

    // ---- out = x - residual_final (transpose back) ----
    {
        float* oblk = out + (size_t)n * CD * TT + t0;
        for (int it = 0; it < 16; it++) {
            int c = (tx >> 4) + 32 * it;
            int t4 = (tx & 15) * 4;
            float4 xv = *(const float4*)&xblk[(size_t)c * TT + t4];
            float4 ov;
            ov.x = xv.x - Rs[(t4 + 0) * RST + c];
            ov.y = xv.y - Rs[(t4 + 1) * RST + c];
            ov.z = xv.z - Rs[(t4 + 2) * RST + c];
            ov.w = xv.w - Rs[(t4 + 3) * RST + c];
            *(float4*)&oblk[(size_t)c * TT + t4] = ov;
        }
    }

    // ---- last-CTA drain: loss + perplexity, restore global state ----
    __syncthreads();
    if (tx == 0) {
        __threadfence();
        flag[0] = (atomicAdd(&g_done, 1) == NBLK - 1) ? 1 : 0;
    }
    __syncthreads();
    if (flag[0]) {
        __threadfence();
        float ls = 0.f;
        for (int i = tx; i < QL * NBLK; i += NTHR) ls += g_losspart[i];
        ls = block_reduce_512(ls, red);
        float lossval = ls / ((float)NTOK * (float)CD * (float)QL);

        float ptot = 0.f;
        for (int qq = 0; qq < QL; qq++) {
            float s = 0.f;
            for (int k = tx; k < KCODES; k += NTHR) {
                float p = (float)g_hist[qq * KCODES + k] * (1.0f / 32768.0f);
                s += p * logf(p + 1e-7f);
            }
            s = block_reduce_512(s, red);
            if (tx == 0) ptot += expf(-s);
        }
        if (tx == 0) {
            if (out_size >= OUT_ELEMS + 2) {
                out[OUT_ELEMS]     = lossval;
                out[OUT_ELEMS + 1] = ptot / (float)QL;
            } else if (out_size == OUT_ELEMS + 1) {
                out[OUT_ELEMS] = lossval;
            }
        }
        for (int i = tx; i < QL * KCODES; i += NTHR) g_hist[i] = 0;
        if (tx == 0) { g_done = 0; __threadfence(); }
    }
}

extern "C" void kernel_launch(void* const* d_in, const int* in_sizes, int n_in,
                              void* d_out, int out_size) {
    const float* x  = (const float*)d_in[0];
    const float* cb = (const float*)d_in[1];
    if (n_in >= 2 && in_sizes[0] == QL * KCODES * CD &&
        in_sizes[1] == NBATCH * CD * TT) {
        const float* tmp = x; x = cb; cb = tmp;
    }
    float* out = (float*)d_out;

    cudaFuncSetAttribute(vq_main_kernel,
                         cudaFuncAttributeMaxDynamicSharedMemorySize, SMEM_BYTES);

    cbnorm_kernel<<<(QL * KCODES * 32 + 255) / 256, 256>>>(cb);
    vq_main_kernel<<<NBLK, NTHR, SMEM_BYTES>>>(x, cb, out, out_size);
}

// round 11
// speedup vs baseline: 1.2776x; 1.2776x over previous
#include <cuda_runtime.h>
#include <math.h>
#include <stdint.h>

// ResidualVQ on B200 (sm_100 base target) — legacy tensor-core tf32
// mma.sync distance GEMM + exact reference-replica argmin rescue.
// R11: warp-private B staging, zero per-phase CTA barriers (was 768).
//
// x: (32, 512, 1024) fp32, codebooks: (6, 1024, 512) fp32.
// out = x - residual_final, + loss & perplexity scalars appended.

#define QL      6
#define KCODES  1024
#define CD      512
#define TT      1024
#define NBATCH  32
#define NTOK    (NBATCH * TT)        // 32768
#define TILE_T  64
#define NBLK    (NTOK / TILE_T)      // 512
#define NTHR    256
#define NPASS   2                    // code passes per layer (512 codes each)
#define PCODES  512
#define KP      8                    // c per phase (one mma k-tile)
#define NPH     (CD / KP)            // 64 phases per pass
#define BST     12                   // staged-B words per code (8 + pad)
#define WBUF    (TILE_T * BST)       // 768 words: one buffer (64 codes)
#define RST     520                  // Rs words per token (512 + pad)
#define OUT_ELEMS (NBATCH * CD * TT)
#define MARGIN  0.25f
#define NSLOT   16                   // 2 passes x 8 warps
#define FINF    3.4e38f

// ---- smem word offsets ----
#define W_RS    0
#define W_B     (TILE_T * RST)                  // 33280; 8 warps x 2 x 768
#define W_CN    (W_B + 16 * WBUF)               // 45568
#define W_CV    (W_CN + KCODES)                 // 46592
#define W_CI    (W_CV + TILE_T * NSLOT * 3)     // 49664
#define W_RN    (W_CI + TILE_T * NSLOT * 3)     // 52736
#define W_IDX   (W_RN + TILE_T)
#define W_RED   (W_IDX + TILE_T)
#define W_FLAG  (W_RED + 8)
#define SMEM_WORDS (W_FLAG + 2)
#define SMEM_BYTES (SMEM_WORDS * 4)             // ~211.5 KB

__device__ float g_cbnorm[QL * KCODES];
__device__ int   g_hist[QL * KCODES];
__device__ float g_losspart[QL * NBLK];
__device__ int   g_done;

// ---------------- tensor-core helpers (sm_80+ base ISA) ----------------
__device__ __forceinline__ uint32_t f2tf(float f) {
    uint32_t r; asm("cvt.rna.tf32.f32 %0, %1;" : "=r"(r) : "f"(f)); return r;
}
__device__ __forceinline__ void mma8(float* d, uint32_t a0, uint32_t a1,
                                     uint32_t a2, uint32_t a3,
                                     uint32_t b0, uint32_t b1) {
    asm volatile(
        "mma.sync.aligned.m16n8k8.row.col.f32.tf32.tf32.f32 "
        "{%0,%1,%2,%3}, {%4,%5,%6,%7}, {%8,%9}, {%0,%1,%2,%3};"
        : "+f"(d[0]), "+f"(d[1]), "+f"(d[2]), "+f"(d[3])
        : "r"(a0), "r"(a1), "r"(a2), "r"(a3), "r"(b0), "r"(b1));
}

// ---------------- replica arithmetic (bit-matches reference) ----------------
__global__ void cbnorm_kernel(const float* __restrict__ cb) {
    int w    = (blockIdx.x * blockDim.x + threadIdx.x) >> 5;
    int lane = threadIdx.x & 31;
    if (w >= QL * KCODES) return;
    const float* row = cb + (size_t)w * CD;
    float a = 0.f;
    #pragma unroll
    for (int i = 0; i < CD / 32; i++) {
        float v = row[lane + 32 * i];
        a = __fadd_rn(a, __fmul_rn(v, v));
    }
    #pragma unroll
    for (int o = 16; o; o >>= 1)
        a = __fadd_rn(a, __shfl_down_sync(0xffffffffu, a, o));
    if (lane == 0) g_cbnorm[w] = a;
}

// Exact replica distance: serial ascending-k FFMA dot + fp32 rounding grid.
__device__ float replica_dist(const float* __restrict__ rtok,
                              const float* __restrict__ crow,
                              float Rn, float cn) {
    float m = 0.f;
    for (int c = 0; c < CD; c += 4) {
        float4 b = *(const float4*)&crow[c];
        m = __fmaf_rn(rtok[c + 0], b.x, m);
        m = __fmaf_rn(rtok[c + 1], b.y, m);
        m = __fmaf_rn(rtok[c + 2], b.z, m);
        m = __fmaf_rn(rtok[c + 3], b.w, m);
    }
    return __fadd_rn(__fsub_rn(Rn, __fmul_rn(2.f, m)), cn);
}

__device__ float block_reduce_256(float v, float* sh) {
    int t = threadIdx.x;
    #pragma unroll
    for (int o = 16; o; o >>= 1) v += __shfl_down_sync(0xffffffffu, v, o);
    if ((t & 31) == 0) sh[t >> 5] = v;
    __syncthreads();
    float r = 0.f;
    if (t < 8) {
        r = sh[t];
        #pragma unroll
        for (int o = 4; o; o >>= 1) r += __shfl_down_sync(0x000000ffu, r, o, 8);
    }
    __syncthreads();
    return r;
}

// Merge this lane's sorted lex triple with lane^off's triple.
__device__ __forceinline__ void lexmerge3(float* v, int* idx, int off) {
    float wv0 = __shfl_xor_sync(0xffffffffu, v[0], off);
    float wv1 = __shfl_xor_sync(0xffffffffu, v[1], off);
    float wv2 = __shfl_xor_sync(0xffffffffu, v[2], off);
    int   wi0 = __shfl_xor_sync(0xffffffffu, idx[0], off);
    int   wi1 = __shfl_xor_sync(0xffffffffu, idx[1], off);
    int   wi2 = __shfl_xor_sync(0xffffffffu, idx[2], off);
    float av[3] = {v[0], v[1], v[2]};
    int   ai[3] = {idx[0], idx[1], idx[2]};
    float bv[3] = {wv0, wv1, wv2};
    int   bi[3] = {wi0, wi1, wi2};
    int a = 0, b = 0;
    #pragma unroll
    for (int o = 0; o < 3; o++) {
        bool tA = (b >= 3) || (a < 3 && (av[a] < bv[b] ||
                   (av[a] == bv[b] && ai[a] <= bi[b])));
        if (tA) { v[o] = av[a]; idx[o] = ai[a]; a++; }
        else    { v[o] = bv[b]; idx[o] = bi[b]; b++; }
    }
}

__device__ __forceinline__ void top2_ins(float nv, int nc, float* v, int* idx) {
    if (nv < v[0] || (nv == v[0] && nc < idx[0])) {
        v[1] = v[0]; idx[1] = idx[0]; v[0] = nv; idx[0] = nc;
    } else if (nv < v[1] || (nv == v[1] && nc < idx[1])) {
        v[1] = nv; idx[1] = nc;
    }
}

// ---------------- main kernel ----------------
__global__ __launch_bounds__(NTHR, 1)
void vq_main_kernel(const float* __restrict__ x, const float* __restrict__ cb,
                    float* __restrict__ out, int out_size) {
    extern __shared__ float smem[];
    float*    Rs   = smem + W_RS;                 // [64][520] residual
    uint32_t* Bst  = (uint32_t*)(smem + W_B);     // per-warp 2x[64][12] tf32
    float*    cn_s = smem + W_CN;                 // [1024] replica code norms
    float*    cd_v = smem + W_CV;                 // [64][16][3] cand values
    int*      cd_i = (int*)(smem + W_CI);
    float*    Rn_s = smem + W_RN;                 // [64] replica ||r||^2
    int*      idxs = (int*)(smem + W_IDX);
    float*    red  = smem + W_RED;
    int*      flag = (int*)(smem + W_FLAG);

    const int tx   = threadIdx.x;
    const int wid  = tx >> 5;
    const int lane = tx & 31;
    const int lg   = lane >> 2;    // 0..7
    const int la   = lane & 3;     // 0..3
    const int blk  = blockIdx.x;
    const int n    = blk >> 4;
    const int t0   = (blk & 15) << 6;
    const float* xblk = x + (size_t)n * CD * TT + t0;

    uint32_t* Bw = Bst + wid * 2 * WBUF;   // this warp's double buffer

    // ---- transpose x into Rs[tok][c] ----
    for (int it = 0; it < 32; it++) {
        int c = (tx >> 4) + 16 * it;
        int t4 = (tx & 15) * 4;
        float4 v = *(const float4*)&xblk[(size_t)c * TT + t4];
        Rs[(t4 + 0) * RST + c] = v.x;
        Rs[(t4 + 1) * RST + c] = v.y;
        Rs[(t4 + 2) * RST + c] = v.z;
        Rs[(t4 + 3) * RST + c] = v.w;
    }
    __syncthreads();

    // ---- initial replica Rn (XLA warp-reduce pattern) ----
    for (int t = 0; t < 8; t++) {
        int tok = wid * 8 + t;
        const float* rr = Rs + tok * RST;
        float a = 0.f;
        #pragma unroll
        for (int i = 0; i < 16; i++) {
            float r = rr[lane + 32 * i];
            a = __fadd_rn(a, __fmul_rn(r, r));
        }
        #pragma unroll
        for (int o = 16; o; o >>= 1)
            a = __fadd_rn(a, __shfl_down_sync(0xffffffffu, a, o));
        if (lane == 0) Rn_s[tok] = a;
    }
    __syncthreads();

    for (int q = 0; q < QL; q++) {
        const float* cbq = cb + (size_t)q * KCODES * CD;
        for (int i = tx; i < KCODES; i += NTHR) cn_s[i] = g_cbnorm[q * KCODES + i];
        __syncthreads();   // cn_s ready; Rs stable for both passes

        for (int pass = 0; pass < NPASS; pass++) {
            // this warp owns codes  pass*512 + wid*64 + (0..63)
            const int cbase = pass * PCODES + wid * TILE_T;
            float ac[4][8][4];
            #pragma unroll
            for (int mt = 0; mt < 4; mt++)
                #pragma unroll
                for (int nt = 0; nt < 8; nt++)
                    #pragma unroll
                    for (int e = 0; e < 4; e++) ac[mt][nt][e] = 0.f;

            // stage phase 0 into buf0 (warp-local; lane -> codes lane, lane+32)
            #pragma unroll
            for (int h = 0; h < 2; h++) {
                int j = lane + 32 * h;
                const float* s = cbq + (size_t)(cbase + j) * CD;
                float4 v0 = *(const float4*)s;
                float4 v1 = *(const float4*)(s + 4);
                uint4 u0 = make_uint4(f2tf(v0.x), f2tf(v0.y), f2tf(v0.z), f2tf(v0.w));
                uint4 u1 = make_uint4(f2tf(v1.x), f2tf(v1.y), f2tf(v1.z), f2tf(v1.w));
                *(uint4*)&Bw[j * BST] = u0;
                *(uint4*)&Bw[j * BST + 4] = u1;
            }
            __syncwarp();

            for (int p = 0; p < NPH; p++) {
                float4 pre0, pre1, pre2, pre3;
                if (p + 1 < NPH) {   // prefetch next phase (this warp's codes)
                    const float* s0 = cbq + (size_t)(cbase + lane) * CD + (p + 1) * KP;
                    const float* s1 = cbq + (size_t)(cbase + lane + 32) * CD + (p + 1) * KP;
                    pre0 = *(const float4*)s0; pre1 = *(const float4*)(s0 + 4);
                    pre2 = *(const float4*)s1; pre3 = *(const float4*)(s1 + 4);
                }
                const uint32_t* Bb = Bw + (p & 1) * WBUF;
                uint32_t b0[8], b1[8];
                #pragma unroll
                for (int nt = 0; nt < 8; nt++) {
                    uint2 bb = *(const uint2*)&Bb[(nt * 8 + lg) * BST + 2 * la];
                    b0[nt] = bb.x; b1[nt] = bb.y;
                }
                const int cb0 = p * KP + 2 * la;
                #pragma unroll
                for (int mt = 0; mt < 4; mt++) {
                    int ta = 16 * mt + lg;
                    float2 lo = *(const float2*)&Rs[ta * RST + cb0];
                    float2 hi = *(const float2*)&Rs[(ta + 8) * RST + cb0];
                    uint32_t a0 = f2tf(lo.x), a2 = f2tf(lo.y);
                    uint32_t a1 = f2tf(hi.x), a3 = f2tf(hi.y);
                    #pragma unroll
                    for (int nt = 0; nt < 8; nt++)
                        mma8(ac[mt][nt], a0, a1, a2, a3, b0[nt], b1[nt]);
                }
                if (p + 1 < NPH) {   // stage next phase into other buffer
                    uint32_t* dst = Bw + ((p + 1) & 1) * WBUF;
                    uint4 u0 = make_uint4(f2tf(pre0.x), f2tf(pre0.y), f2tf(pre0.z), f2tf(pre0.w));
                    uint4 u1 = make_uint4(f2tf(pre1.x), f2tf(pre1.y), f2tf(pre1.z), f2tf(pre1.w));
                    uint4 u2 = make_uint4(f2tf(pre2.x), f2tf(pre2.y), f2tf(pre2.z), f2tf(pre2.w));
                    uint4 u3 = make_uint4(f2tf(pre3.x), f2tf(pre3.y), f2tf(pre3.z), f2tf(pre3.w));
                    *(uint4*)&dst[lane * BST] = u0;
                    *(uint4*)&dst[lane * BST + 4] = u1;
                    *(uint4*)&dst[(lane + 32) * BST] = u2;
                    *(uint4*)&dst[(lane + 32) * BST + 4] = u3;
                }
                __syncwarp();   // warp-local ordering only — no CTA barrier
            }

            // ---- epilogue: dist = (Rn - 2*dot) + cn ; per-warp top-3 ----
            const int slot = pass * 8 + wid;
            #pragma unroll
            for (int mt = 0; mt < 4; mt++) {
                int tA = 16 * mt + lg, tB = tA + 8;
                float RnA = Rn_s[tA], RnB = Rn_s[tB];
                float vA[3] = {FINF, FINF, FINF}; int iA[3] = {0, 1, 2};
                float vB[3] = {FINF, FINF, FINF}; int iB[3] = {0, 1, 2};
                #pragma unroll
                for (int nt = 0; nt < 8; nt++) {
                    int c0 = cbase + nt * 8 + 2 * la;
                    float cn0 = cn_s[c0], cn1 = cn_s[c0 + 1];
                    top2_ins((RnA - 2.f * ac[mt][nt][0]) + cn0, c0,     vA, iA);
                    top2_ins((RnA - 2.f * ac[mt][nt][1]) + cn1, c0 + 1, vA, iA);
                    top2_ins((RnB - 2.f * ac[mt][nt][2]) + cn0, c0,     vB, iB);
                    top2_ins((RnB - 2.f * ac[mt][nt][3]) + cn1, c0 + 1, vB, iB);
                }
                lexmerge3(vA, iA, 1); lexmerge3(vA, iA, 2);
                lexmerge3(vB, iB, 1); lexmerge3(vB, iB, 2);
                if (la == 0) {
                    #pragma unroll
                    for (int j = 0; j < 3; j++) {
                        cd_v[(tA * NSLOT + slot) * 3 + j] = vA[j];
                        cd_i[(tA * NSLOT + slot) * 3 + j] = iA[j];
                        cd_v[(tB * NSLOT + slot) * 3 + j] = vB[j];
                        cd_i[(tB * NSLOT + slot) * 3 + j] = iB[j];
                    }
                }
            }
            // no CTA barrier between passes: Bw is warp-private,
            // cd slots are (pass,warp)-unique, Rs/Rn/cn read-only here.
        }
        __syncthreads();   // all candidate slots visible

        // ---- decision: global lex-min; margin -> exact replica rescore ----
        if (tx < TILE_T) {
            const int tok = tx;
            const float* cvp = cd_v + tok * NSLOT * 3;
            const int*   cip = cd_i + tok * NSLOT * 3;
            float v1 = FINF, v2 = FINF; int i1 = 0x7fffffff;
            for (int j = 0; j < NSLOT * 3; j++) {
                float v = cvp[j]; int c = cip[j];
                if (v < v1 || (v == v1 && c < i1)) { v2 = v1; v1 = v; i1 = c; }
                else if (v < v2) { v2 = v; }
            }
            int id = i1;
            if (v2 - v1 < MARGIN) {
                const float Rn = Rn_s[tok];
                const float* rtok = Rs + tok * RST;
                float bv = FINF; int bi = 0x7fffffff;
                float lim = v1 + MARGIN;
                for (int j = 0; j < NSLOT * 3; j++) {
                    if (cvp[j] <= lim) {
                        int c = cip[j];
                        float d = replica_dist(rtok, cbq + (size_t)c * CD, Rn, cn_s[c]);
                        if (d < bv || (d == bv && c < bi)) { bv = d; bi = c; }
                    }
                }
                id = bi;
            }
            idxs[tok] = id;
            atomicAdd(&g_hist[q * KCODES + id], 1);
        }
        __syncthreads();

        // ---- STE-replica residual update + new replica Rn ----
        for (int t = 0; t < 8; t++) {
            int tok = wid * 8 + t;
            const float* row = cbq + (size_t)idxs[tok] * CD;
            float* rr = Rs + tok * RST;
            float a = 0.f;
            #pragma unroll
            for (int i = 0; i < 16; i++) {
                int c = lane + 32 * i;
                float r  = rr[c];
                float xd = row[c];
                float tt = __fsub_rn(xd, r);
                float qv = __fadd_rn(r, tt);
                float rn = __fsub_rn(r, qv);
                rr[c] = rn;
                a = __fadd_rn(a, __fmul_rn(rn, rn));
            }
            #pragma unroll
            for (int o = 16; o; o >>= 1)
                a = __fadd_rn(a, __shfl_down_sync(0xffffffffu, a, o));
            if (lane == 0) Rn_s[tok] = a;
        }
        __syncthreads();
        if (tx < 32) {
            float s = Rn_s[tx] + Rn_s[tx + 32];
            #pragma unroll
            for (int o = 16; o; o >>= 1) s += __shfl_down_sync(0xffffffffu, s, o);
            if (tx == 0) g_losspart[q * NBLK + blk] = s;
        }
        __syncthreads();
    }

    // ---- out = x - residual_final (transpose back) ----
    {
        float* oblk = out + (size_t)n * CD * TT + t0;
        for (int it = 0; it < 32; it++) {
            int c = (tx >> 4) + 16 * it;
            int t4 = (tx & 15) * 4;
            float4 xv = *(const float4*)&xblk[(size_t)c * TT + t4];
            float4 ov;
            ov.x = xv.x - Rs[(t4 + 0) * RST + c];
            ov.y = xv.y - Rs[(t4 + 1) * RST + c];
            ov.z = xv.z - Rs[(t4 + 2) * RST + c];
            ov.w = xv.w - Rs[(t4 + 3) * RST + c];
            *(float4*)&oblk[(size_t)c * TT + t4] = ov;
        }
    }

    // ---- last-CTA drain: loss + perplexity, restore global state ----
    __syncthreads();
    if (tx == 0) {
        __threadfence();
        flag[0] = (atomicAdd(&g_done, 1) == NBLK - 1) ? 1 : 0;
    }
    __syncthreads();
    if (flag[0]) {
        __threadfence();
        float ls = 0.f;
        for (int i = tx; i < QL * NBLK; i += NTHR) ls += g_losspart[i];
        ls = block_reduce_256(ls, red);
        float lossval = ls / ((float)NTOK * (float)CD * (float)QL);

        float ptot = 0.f;
        for (int qq = 0; qq < QL; qq++) {
            float s = 0.f;
            for (int k = tx; k < KCODES; k += NTHR) {
                float p = (float)g_hist[qq * KCODES + k] * (1.0f / 32768.0f);
                s += p * logf(p + 1e-7f);
            }
            s = block_reduce_256(s, red);
            if (tx == 0) ptot += expf(-s);
        }
        if (tx == 0) {
            if (out_size >= OUT_ELEMS + 2) {
                out[OUT_ELEMS]     = lossval;
                out[OUT_ELEMS + 1] = ptot / (float)QL;
            } else if (out_size == OUT_ELEMS + 1) {
                out[OUT_ELEMS] = lossval;
            }
        }
        for (int i = tx; i < QL * KCODES; i += NTHR) g_hist[i] = 0;
        if (tx == 0) { g_done = 0; __threadfence(); }
    }
}

extern "C" void kernel_launch(void* const* d_in, const int* in_sizes, int n_in,
                              void* d_out, int out_size) {
    const float* x  = (const float*)d_in[0];
    const float* cb = (const float*)d_in[1];
    if (n_in >= 2 && in_sizes[0] == QL * KCODES * CD &&
        in_sizes[1] == NBATCH * CD * TT) {
        const float* tmp = x; x = cb; cb = tmp;
    }
    float* out = (float*)d_out;

    cudaFuncSetAttribute(vq_main_kernel,
                         cudaFuncAttributeMaxDynamicSharedMemorySize, SMEM_BYTES);

    cbnorm_kernel<<<(QL * KCODES * 32 + 255) / 256, 256>>>(cb);
    vq_main_kernel<<<NBLK, NTHR, SMEM_BYTES>>>(x, cb, out, out_size);
}

// round 13
// speedup vs baseline: 1.3843x; 1.0835x over previous
#include <cuda_runtime.h>
#include <math.h>
#include <stdint.h>

// ResidualVQ on B200 (sm_100 base target) — legacy tensor-core tf32
// mma.sync distance GEMM + exact reference-replica argmin rescue.
// R12: 16 warps/CTA, warp-private B staging, zero hot-loop CTA barriers.
//
// x: (32, 512, 1024) fp32, codebooks: (6, 1024, 512) fp32.
// out = x - residual_final, + loss & perplexity scalars appended.

#define QL      6
#define KCODES  1024
#define CD      512
#define TT      1024
#define NBATCH  32
#define NTOK    (NBATCH * TT)        // 32768
#define TILE_T  64
#define NBLK    (NTOK / TILE_T)      // 512
#define NTHR    512
#define NWARP   16
#define NPASS   2                    // code passes per layer (512 codes each)
#define PCODES  512
#define WCODES  32                   // codes per warp per pass
#define KP      8                    // c per phase (one mma k-tile)
#define NPH     (CD / KP)            // 64 phases per pass
#define BST     12                   // staged-B words per code (8 + pad)
#define WBUF    (WCODES * BST)       // 384 words: one buffer (32 codes)
#define RST     520                  // Rs words per token (512 + pad)
#define OUT_ELEMS (NBATCH * CD * TT)
#define MARGIN  0.25f
#define NSLOT   32                   // 2 passes x 16 warps
#define FINF    3.4e38f

// ---- smem word offsets ----
#define W_RS    0
#define W_B     (TILE_T * RST)                  // 33280; 16 warps x 2 x 384
#define W_CN    (W_B + NWARP * 2 * WBUF)        // 45568
#define W_CV    (W_CN + KCODES)                 // 46592
#define W_CI    (W_CV + TILE_T * NSLOT * 2)     // 50688
#define W_RN    (W_CI + TILE_T * NSLOT * 2)     // 54784
#define W_IDX   (W_RN + TILE_T)
#define W_RED   (W_IDX + TILE_T)
#define W_FLAG  (W_RED + 16)
#define SMEM_WORDS (W_FLAG + 2)
#define SMEM_BYTES (SMEM_WORDS * 4)             // ~214.6 KB

__device__ float g_cbnorm[QL * KCODES];
__device__ int   g_hist[QL * KCODES];
__device__ float g_losspart[QL * NBLK];
__device__ int   g_done;

// ---------------- tensor-core helpers (sm_80+ base ISA) ----------------
__device__ __forceinline__ uint32_t f2tf(float f) {
    uint32_t r; asm("cvt.rna.tf32.f32 %0, %1;" : "=r"(r) : "f"(f)); return r;
}
__device__ __forceinline__ void mma8(float* d, uint32_t a0, uint32_t a1,
                                     uint32_t a2, uint32_t a3,
                                     uint32_t b0, uint32_t b1) {
    asm volatile(
        "mma.sync.aligned.m16n8k8.row.col.f32.tf32.tf32.f32 "
        "{%0,%1,%2,%3}, {%4,%5,%6,%7}, {%8,%9}, {%0,%1,%2,%3};"
        : "+f"(d[0]), "+f"(d[1]), "+f"(d[2]), "+f"(d[3])
        : "r"(a0), "r"(a1), "r"(a2), "r"(a3), "r"(b0), "r"(b1));
}

// ---------------- replica arithmetic (bit-matches reference) ----------------
__global__ void cbnorm_kernel(const float* __restrict__ cb) {
    int w    = (blockIdx.x * blockDim.x + threadIdx.x) >> 5;
    int lane = threadIdx.x & 31;
    if (w >= QL * KCODES) return;
    const float* row = cb + (size_t)w * CD;
    float a = 0.f;
    #pragma unroll
    for (int i = 0; i < CD / 32; i++) {
        float v = row[lane + 32 * i];
        a = __fadd_rn(a, __fmul_rn(v, v));
    }
    #pragma unroll
    for (int o = 16; o; o >>= 1)
        a = __fadd_rn(a, __shfl_down_sync(0xffffffffu, a, o));
    if (lane == 0) g_cbnorm[w] = a;
}

// Exact replica distance: serial ascending-k FFMA dot + fp32 rounding grid.
__device__ float replica_dist(const float* __restrict__ rtok,
                              const float* __restrict__ crow,
                              float Rn, float cn) {
    float m = 0.f;
    for (int c = 0; c < CD; c += 4) {
        float4 b = *(const float4*)&crow[c];
        m = __fmaf_rn(rtok[c + 0], b.x, m);
        m = __fmaf_rn(rtok[c + 1], b.y, m);
        m = __fmaf_rn(rtok[c + 2], b.z, m);
        m = __fmaf_rn(rtok[c + 3], b.w, m);
    }
    return __fadd_rn(__fsub_rn(Rn, __fmul_rn(2.f, m)), cn);
}

__device__ float block_reduce_512(float v, float* sh) {
    int t = threadIdx.x;
    #pragma unroll
    for (int o = 16; o; o >>= 1) v += __shfl_down_sync(0xffffffffu, v, o);
    if ((t & 31) == 0) sh[t >> 5] = v;
    __syncthreads();
    float r = 0.f;
    if (t < 16) {
        r = sh[t];
        #pragma unroll
        for (int o = 8; o; o >>= 1) r += __shfl_down_sync(0x0000ffffu, r, o, 16);
    }
    __syncthreads();
    return r;
}

// Merge this lane's sorted lex pair with lane^off's pair.
__device__ __forceinline__ void lexmerge2(float* v, int* idx, int off) {
    float wv0 = __shfl_xor_sync(0xffffffffu, v[0], off);
    float wv1 = __shfl_xor_sync(0xffffffffu, v[1], off);
    int   wi0 = __shfl_xor_sync(0xffffffffu, idx[0], off);
    int   wi1 = __shfl_xor_sync(0xffffffffu, idx[1], off);
    float av0 = v[0], av1 = v[1];
    int   ai0 = idx[0], ai1 = idx[1];
    if (wv0 < av0 || (wv0 == av0 && wi0 < ai0)) {
        v[0] = wv0; idx[0] = wi0;
        if (av0 < wv1 || (av0 == wv1 && ai0 <= wi1)) { v[1] = av0; idx[1] = ai0; }
        else                                          { v[1] = wv1; idx[1] = wi1; }
    } else {
        if (wv0 < av1 || (wv0 == av1 && wi0 <= ai1)) { v[1] = wv0; idx[1] = wi0; }
        else                                          { v[1] = av1; idx[1] = ai1; }
    }
}

__device__ __forceinline__ void top2_ins(float nv, int nc, float* v, int* idx) {
    if (nv < v[0] || (nv == v[0] && nc < idx[0])) {
        v[1] = v[0]; idx[1] = idx[0]; v[0] = nv; idx[0] = nc;
    } else if (nv < v[1] || (nv == v[1] && nc < idx[1])) {
        v[1] = nv; idx[1] = nc;
    }
}

// ---------------- main kernel ----------------
__global__ __launch_bounds__(NTHR, 1)
void vq_main_kernel(const float* __restrict__ x, const float* __restrict__ cb,
                    float* __restrict__ out, int out_size) {
    extern __shared__ float smem[];
    float*    Rs   = smem + W_RS;                 // [64][520] residual
    uint32_t* Bst  = (uint32_t*)(smem + W_B);     // per-warp 2x[32][12] tf32
    float*    cn_s = smem + W_CN;                 // [1024] replica code norms
    float*    cd_v = smem + W_CV;                 // [64][32][2] cand values
    int*      cd_i = (int*)(smem + W_CI);
    float*    Rn_s = smem + W_RN;                 // [64] replica ||r||^2
    int*      idxs = (int*)(smem + W_IDX);
    float*    red  = smem + W_RED;
    int*      flag = (int*)(smem + W_FLAG);

    const int tx   = threadIdx.x;
    const int wid  = tx >> 5;
    const int lane = tx & 31;
    const int lg   = lane >> 2;    // 0..7
    const int la   = lane & 3;     // 0..3
    const int blk  = blockIdx.x;
    const int n    = blk >> 4;
    const int t0   = (blk & 15) << 6;
    const float* xblk = x + (size_t)n * CD * TT + t0;

    uint32_t* Bw = Bst + wid * 2 * WBUF;   // this warp's double buffer

    // ---- transpose x into Rs[tok][c] ----
    for (int it = 0; it < 16; it++) {
        int c = (tx >> 4) + 32 * it;
        int t4 = (tx & 15) * 4;
        float4 v = *(const float4*)&xblk[(size_t)c * TT + t4];
        Rs[(t4 + 0) * RST + c] = v.x;
        Rs[(t4 + 1) * RST + c] = v.y;
        Rs[(t4 + 2) * RST + c] = v.z;
        Rs[(t4 + 3) * RST + c] = v.w;
    }
    __syncthreads();

    // ---- initial replica Rn (XLA warp-reduce pattern); warp -> 4 tokens ----
    for (int t = 0; t < 4; t++) {
        int tok = wid * 4 + t;
        const float* rr = Rs + tok * RST;
        float a = 0.f;
        #pragma unroll
        for (int i = 0; i < 16; i++) {
            float r = rr[lane + 32 * i];
            a = __fadd_rn(a, __fmul_rn(r, r));
        }
        #pragma unroll
        for (int o = 16; o; o >>= 1)
            a = __fadd_rn(a, __shfl_down_sync(0xffffffffu, a, o));
        if (lane == 0) Rn_s[tok] = a;
    }
    __syncthreads();

    for (int q = 0; q < QL; q++) {
        const float* cbq = cb + (size_t)q * KCODES * CD;
        for (int i = tx; i < KCODES; i += NTHR) cn_s[i] = g_cbnorm[q * KCODES + i];
        __syncthreads();   // cn_s ready; Rs stable for both passes

        for (int pass = 0; pass < NPASS; pass++) {
            // this warp owns codes  pass*512 + wid*32 + (0..31)
            const int cbase = pass * PCODES + wid * WCODES;
            float ac[4][4][4];
            #pragma unroll
            for (int mt = 0; mt < 4; mt++)
                #pragma unroll
                for (int nt = 0; nt < 4; nt++)
                    #pragma unroll
                    for (int e = 0; e < 4; e++) ac[mt][nt][e] = 0.f;

            // stage phase 0 into buf0 (warp-local; lane -> code lane)
            {
                const float* s = cbq + (size_t)(cbase + lane) * CD;
                float4 v0 = *(const float4*)s;
                float4 v1 = *(const float4*)(s + 4);
                uint4 u0 = make_uint4(f2tf(v0.x), f2tf(v0.y), f2tf(v0.z), f2tf(v0.w));
                uint4 u1 = make_uint4(f2tf(v1.x), f2tf(v1.y), f2tf(v1.z), f2tf(v1.w));
                *(uint4*)&Bw[lane * BST] = u0;
                *(uint4*)&Bw[lane * BST + 4] = u1;
            }
            __syncwarp();

            for (int p = 0; p < NPH; p++) {
                float4 pre0, pre1;
                if (p + 1 < NPH) {   // prefetch next phase (this warp's codes)
                    const float* s0 = cbq + (size_t)(cbase + lane) * CD + (p + 1) * KP;
                    pre0 = *(const float4*)s0; pre1 = *(const float4*)(s0 + 4);
                }
                const uint32_t* Bb = Bw + (p & 1) * WBUF;
                uint32_t b0[4], b1[4];
                #pragma unroll
                for (int nt = 0; nt < 4; nt++) {
                    uint2 bb = *(const uint2*)&Bb[(nt * 8 + lg) * BST + 2 * la];
                    b0[nt] = bb.x; b1[nt] = bb.y;
                }
                const int cb0 = p * KP + 2 * la;
                #pragma unroll
                for (int mt = 0; mt < 4; mt++) {
                    int ta = 16 * mt + lg;
                    float2 lo = *(const float2*)&Rs[ta * RST + cb0];
                    float2 hi = *(const float2*)&Rs[(ta + 8) * RST + cb0];
                    uint32_t a0 = f2tf(lo.x), a2 = f2tf(lo.y);
                    uint32_t a1 = f2tf(hi.x), a3 = f2tf(hi.y);
                    #pragma unroll
                    for (int nt = 0; nt < 4; nt++)
                        mma8(ac[mt][nt], a0, a1, a2, a3, b0[nt], b1[nt]);
                }
                if (p + 1 < NPH) {   // stage next phase into other buffer
                    uint32_t* dst = Bw + ((p + 1) & 1) * WBUF;
                    uint4 u0 = make_uint4(f2tf(pre0.x), f2tf(pre0.y), f2tf(pre0.z), f2tf(pre0.w));
                    uint4 u1 = make_uint4(f2tf(pre1.x), f2tf(pre1.y), f2tf(pre1.z), f2tf(pre1.w));
                    *(uint4*)&dst[lane * BST] = u0;
                    *(uint4*)&dst[lane * BST + 4] = u1;
                }
                __syncwarp();   // warp-local ordering only — no CTA barrier
            }

            // ---- epilogue: dist = (Rn - 2*dot) + cn ; per-warp top-2 ----
            const int slot = pass * NWARP + wid;
            #pragma unroll
            for (int mt = 0; mt < 4; mt++) {
                int tA = 16 * mt + lg, tB = tA + 8;
                float RnA = Rn_s[tA], RnB = Rn_s[tB];
                float vA[2] = {FINF, FINF}; int iA[2] = {0, 1};
                float vB[2] = {FINF, FINF}; int iB[2] = {0, 1};
                #pragma unroll
                for (int nt = 0; nt < 4; nt++) {
                    int c0 = cbase + nt * 8 + 2 * la;
                    float cn0 = cn_s[c0], cn1 = cn_s[c0 + 1];
                    top2_ins((RnA - 2.f * ac[mt][nt][0]) + cn0, c0,     vA, iA);
                    top2_ins((RnA - 2.f * ac[mt][nt][1]) + cn1, c0 + 1, vA, iA);
                    top2_ins((RnB - 2.f * ac[mt][nt][2]) + cn0, c0,     vB, iB);
                    top2_ins((RnB - 2.f * ac[mt][nt][3]) + cn1, c0 + 1, vB, iB);
                }
                lexmerge2(vA, iA, 1); lexmerge2(vA, iA, 2);
                lexmerge2(vB, iB, 1); lexmerge2(vB, iB, 2);
                if (la == 0) {
                    cd_v[(tA * NSLOT + slot) * 2 + 0] = vA[0];
                    cd_v[(tA * NSLOT + slot) * 2 + 1] = vA[1];
                    cd_i[(tA * NSLOT + slot) * 2 + 0] = iA[0];
                    cd_i[(tA * NSLOT + slot) * 2 + 1] = iA[1];
                    cd_v[(tB * NSLOT + slot) * 2 + 0] = vB[0];
                    cd_v[(tB * NSLOT + slot) * 2 + 1] = vB[1];
                    cd_i[(tB * NSLOT + slot) * 2 + 0] = iB[0];
                    cd_i[(tB * NSLOT + slot) * 2 + 1] = iB[1];
                }
            }
            // no CTA barrier between passes: Bw is warp-private,
            // cd slots are (pass,warp)-unique, Rs/Rn/cn read-only here.
        }
        __syncthreads();   // all candidate slots visible

        // ---- decision: global lex-min; margin -> exact replica rescore ----
        if (tx < TILE_T) {
            const int tok = tx;
            const float* cvp = cd_v + tok * NSLOT * 2;
            const int*   cip = cd_i + tok * NSLOT * 2;
            float v1 = FINF, v2 = FINF; int i1 = 0x7fffffff;
            for (int j = 0; j < NSLOT * 2; j++) {
                float v = cvp[j]; int c = cip[j];
                if (v < v1 || (v == v1 && c < i1)) { v2 = v1; v1 = v; i1 = c; }
                else if (v < v2) { v2 = v; }
            }
            int id = i1;
            if (v2 - v1 < MARGIN) {
                const float Rn = Rn_s[tok];
                const float* rtok = Rs + tok * RST;
                float bv = FINF; int bi = 0x7fffffff;
                float lim = v1 + MARGIN;
                for (int j = 0; j < NSLOT * 2; j++) {
                    if (cvp[j] <= lim) {
                        int c = cip[j];
                        float d = replica_dist(rtok, cbq + (size_t)c * CD, Rn, cn_s[c]);
                        if (d < bv || (d == bv && c < bi)) { bv = d; bi = c; }
                    }
                }
                id = bi;
            }
            idxs[tok] = id;
            atomicAdd(&g_hist[q * KCODES + id], 1);
        }
        __syncthreads();

        // ---- STE-replica residual update + new replica Rn ----
        for (int t = 0; t < 4; t++) {
            int tok = wid * 4 + t;
            const float* row = cbq + (size_t)idxs[tok] * CD;
            float* rr = Rs + tok * RST;
            float a = 0.f;
            #pragma unroll
            for (int i = 0; i < 16; i++) {
                int c = lane + 32 * i;
                float r  = rr[c];
                float xd = row[c];
                float tt = __fsub_rn(xd, r);
                float qv = __fadd_rn(r, tt);
                float rn = __fsub_rn(r, qv);
                rr[c] = rn;
                a = __fadd_rn(a, __fmul_rn(rn, rn));
            }
            #pragma unroll
            for (int o = 16; o; o >>= 1)
                a = __fadd_rn(a, __shfl_down_sync(0xffffffffu, a, o));
            if (lane == 0) Rn_s[tok] = a;
        }
        __syncthreads();
        if (tx < 32) {
            float s = Rn_s[tx] + Rn_s[tx + 32];
            #pragma unroll
            for (int o = 16; o; o >>= 1) s += __shfl_down_sync(0xffffffffu, s, o);
            if (tx == 0) g_losspart[q * NBLK + blk] = s;
        }
        __syncthreads();
    }

    // ---- out = x - residual_final (transpose back) ----
    {
        float* oblk = out + (size_t)n * CD * TT + t0;
        for (int it = 0; it < 16; it++) {
            int c = (tx >> 4) + 32 * it;
            int t4 = (tx & 15) * 4;
            float4 xv = *(const float4*)&xblk[(size_t)c * TT + t4];
            float4 ov;
            ov.x = xv.x - Rs[(t4 + 0) * RST + c];
            ov.y = xv.y - Rs[(t4 + 1) * RST + c];
            ov.z = xv.z - Rs[(t4 + 2) * RST + c];
            ov.w = xv.w - Rs[(t4 + 3) * RST + c];
            *(float4*)&oblk[(size_t)c * TT + t4] = ov;
        }
    }

    // ---- last-CTA drain: loss + perplexity, restore global state ----
    __syncthreads();
    if (tx == 0) {
        __threadfence();
        flag[0] = (atomicAdd(&g_done, 1) == NBLK - 1) ? 1 : 0;
    }
    __syncthreads();
    if (flag[0]) {
        __threadfence();
        float ls = 0.f;
        for (int i = tx; i < QL * NBLK; i += NTHR) ls += g_losspart[i];
        ls = block_reduce_512(ls, red);
        float lossval = ls / ((float)NTOK * (float)CD * (float)QL);

        float ptot = 0.f;
        for (int qq = 0; qq < QL; qq++) {
            float s = 0.f;
            for (int k = tx; k < KCODES; k += NTHR) {
                float p = (float)g_hist[qq * KCODES + k] * (1.0f / 32768.0f);
                s += p * logf(p + 1e-7f);
            }
            s = block_reduce_512(s, red);
            if (tx == 0) ptot += expf(-s);
        }
        if (tx == 0) {
            if (out_size >= OUT_ELEMS + 2) {
                out[OUT_ELEMS]     = lossval;
                out[OUT_ELEMS + 1] = ptot / (float)QL;
            } else if (out_size == OUT_ELEMS + 1) {
                out[OUT_ELEMS] = lossval;
            }
        }
        for (int i = tx; i < QL * KCODES; i += NTHR) g_hist[i] = 0;
        if (tx == 0) { g_done = 0; __threadfence(); }
    }
}

extern "C" void kernel_launch(void* const* d_in, const int* in_sizes, int n_in,
                              void* d_out, int out_size) {
    const float* x  = (const float*)d_in[0];
    const float* cb = (const float*)d_in[1];
    if (n_in >= 2 && in_sizes[0] == QL * KCODES * CD &&
        in_sizes[1] == NBATCH * CD * TT) {
        const float* tmp = x; x = cb; cb = tmp;
    }
    float* out = (float*)d_out;

    cudaFuncSetAttribute(vq_main_kernel,
                         cudaFuncAttributeMaxDynamicSharedMemorySize, SMEM_BYTES);

    cbnorm_kernel<<<(QL * KCODES * 32 + 255) / 256, 256>>>(cb);
    vq_main_kernel<<<NBLK, NTHR, SMEM_BYTES>>>(x, cb, out, out_size);
}